// round 11
// baseline (speedup 1.0000x reference)
#include <cuda_runtime.h>
#include <math.h>

#define B_   128
#define T_   512
#define NI   64
#define NH   1024
#define NO   64

#define NJT    33            // 32 rec/fgt j-tiles + 1 dec j-tile
#define KSPLIT 16
#define NCTA   (NJT*KSPLIT)  // 528 -> 4 CTAs/SM co-resident (148 SMs)
#define NTHR   128
#define KSL    64            // k-slice per CTA
#define BK     16
#define NCHUNK (KSL/BK)      // 4
#define JP_CTA 32            // column-pairs per CTA
#define OUTS_CTA 4096        // 128 b * 32 pairs
#define PARTBUF ((size_t)NCTA * OUTS_CTA)
#define SMEM_BYTES (KSL*JP_CTA*8 + 2*BK*B_*4)   // 16KB ws + 16KB hs = 32KB

// ---------------- scratch ------------------------------------------------------
__device__ float g_enc[(size_t)T_ * B_ * NH];          // [t][b][h]
__device__ float g_hidB[3][B_ * NH];                   // [b][h], triple-buffered
__device__ float g_hidT[3][NH * B_];                   // [h][b], triple-buffered
__device__ unsigned long long g_part[2 * PARTBUF];     // step-parity double buffer
__device__ unsigned g_flag[NJT];                       // publish counters per tile
__device__ unsigned g_done[32];                        // per-rec-tile hidden-ready
__device__ unsigned g_decc[KSPLIT];                    // dec consumption per k-slot

// ---------------- helpers ------------------------------------------------------
#define FMA2(d, a, b) asm("fma.rn.f32x2 %0, %1, %2, %0;" : "+l"(d) : "l"(a), "l"(b))
__device__ __forceinline__ unsigned long long dup2(float h) {
    unsigned long long r;
    asm("mov.b64 %0, {%1, %1};" : "=l"(r) : "f"(h));
    return r;
}

// ---------------- reset + init --------------------------------------------------
__global__ void reset_kernel() {
    int i = threadIdx.x;
    if (i < NJT) g_flag[i] = 0;
    if (i < 32) g_done[i] = 0;
    if (i < KSPLIT) g_decc[i] = 0;
}

__global__ void init_hidden_kernel(const float* __restrict__ hinit_w,
                                   const float* __restrict__ hinit_b) {
    int idx = blockIdx.x * blockDim.x + threadIdx.x;
    if (idx < B_ * NH) {
        int hT = idx >> 7;                 // [h][b]
        g_hidT[0][idx] = hinit_w[hT] + hinit_b[hT];
        int hB = idx & (NH - 1);           // [b][h]
        g_hidB[0][idx] = hinit_w[hB] + hinit_b[hB];
    }
}

// ---------------- encoder GEMM (one-shot) ---------------------------------------
__global__ void __launch_bounds__(256) enc_kernel(const float* __restrict__ x,
                                                  const float* __restrict__ enc_w,
                                                  const float* __restrict__ enc_b) {
    __shared__ float xs[32][NI + 1];
    __shared__ float ws[64][NI + 1];
    const int tid = threadIdx.x;
    const int tb0 = blockIdx.x * 32;
    const int h0  = blockIdx.y * 64;

    for (int i = tid; i < 32 * NI; i += 256) {
        int r = i >> 6, c = i & 63;
        int tb = tb0 + r;
        int t = tb >> 7, b = tb & 127;
        xs[r][c] = x[(size_t)b * (T_ * NI) + t * NI + c];
    }
    for (int i = tid; i < 64 * NI; i += 256) {
        int r = i >> 6, c = i & 63;
        ws[r][c] = enc_w[(h0 + r) * NI + c];
    }
    __syncthreads();

    const int rg = tid & 7;
    const int hg = tid >> 3;
    float acc[4][2] = {};
#pragma unroll
    for (int k = 0; k < NI; k++) {
        float w0 = ws[hg * 2 + 0][k];
        float w1 = ws[hg * 2 + 1][k];
#pragma unroll
        for (int j = 0; j < 4; j++) {
            float xv = xs[rg * 4 + j][k];
            acc[j][0] += xv * w0;
            acc[j][1] += xv * w1;
        }
    }
#pragma unroll
    for (int j = 0; j < 4; j++) {
        int tb = tb0 + rg * 4 + j;
#pragma unroll
        for (int q = 0; q < 2; q++) {
            int h = h0 + hg * 2 + q;
            g_enc[(size_t)tb * NH + h] = acc[j][q] + enc_b[h];
        }
    }
}

// ---------------- persistent recurrent kernel ------------------------------------
// CTA: jt = bid>>4 (j-tile of 32 pairs), ks = bid&15 (k-slot of 64).
// Pair p = jt*32+jp: p<1024 -> (rec_w[p,:], fgt_w[p,:]); p>=1024 -> dec cols (2m,2m+1).
// Dataflow flags (no global barrier); hidden triple-buffered; partials parity-buffered.
__global__ void __launch_bounds__(NTHR, 4) persist_kernel(const float* __restrict__ rec_w,
                                                          const float* __restrict__ fgt_w,
                                                          const float* __restrict__ dec_w,
                                                          const float* __restrict__ dec_b,
                                                          float* __restrict__ out,
                                                          int writeHidden) {
    extern __shared__ __align__(16) char smem[];
    unsigned long long* ws = (unsigned long long*)smem;     // [64 k][32 jp] (wA,wB)
    float* hsf = (float*)(smem + KSL * JP_CTA * 8);         // [2][16 k][128 b]

    const int tid = threadIdx.x;
    const int bid = blockIdx.x;
    const int jt  = bid >> 4;        // 0..32
    const int ks  = bid & 15;        // 0..15
    const int j0  = jt * JP_CTA;
    const int kbase = ks * KSL;
    const bool isDec = (jt == 32);

    const int jg = tid & 7;          // 8 j-groups of 4 pairs
    const int bg = tid >> 3;         // 16 b-groups of 8 rows

    // ---- weights -> SMEM once ----
    for (int i = tid; i < KSL * JP_CTA; i += NTHR) {
        int k = i & (KSL - 1), jp = i >> 6;
        int p = j0 + jp;
        int gk = kbase + k;
        float a, b;
        if (p < 1024) { a = rec_w[p * NH + gk]; b = fgt_w[p * NH + gk]; }
        else { int m = p - 1024; a = dec_w[(2 * m) * NH + gk]; b = dec_w[(2 * m + 1) * NH + gk]; }
        ws[k * JP_CTA + jp] = ((unsigned long long)__float_as_uint(b) << 32) | __float_as_uint(a);
    }
    __syncthreads();

    // combine-phase identities: 16 CTAs of a jt cover 128 b; each thread: 1 b x 2 jp
    const int bloc = ks * 8 + (tid >> 4);    // b this thread combines
    const int jpb  = (tid & 15) * 2;         // 2 consecutive jp
    float2 db01 = make_float2(0, 0), db23 = db01;
    if (isDec) {
        db01 = *(const float2*)(dec_b + jpb * 2);
        db23 = *(const float2*)(dec_b + jpb * 2 + 2);
    }

    int cur = 0;
    for (int t = 0; t <= T_; t++) {
        const int nxt = (cur + 1 == 3) ? 0 : cur + 1;
        const bool work = (t < T_) || isDec;

        if (work) {
            // ---- wait: producer tiles of this k-slot reached level t ----
            if (tid == 0) {
                unsigned target = (unsigned)KSPLIT * (unsigned)t;
                while (((volatile unsigned*)g_done)[2 * ks]     < target) __nanosleep(20);
                while (((volatile unsigned*)g_done)[2 * ks + 1] < target) __nanosleep(20);
                __threadfence();
            }
            __syncthreads();

            // ================= GEMM over K-slice =================
            const float* __restrict__ hsrc = g_hidT[cur] + kbase * B_;
            float4 pf[4];
#pragma unroll
            for (int i = 0; i < 4; i++) {
                int slot = i * NTHR + tid;
                int row = slot >> 5, c4 = slot & 31;
                pf[i] = __ldcg((const float4*)(hsrc + row * B_ + c4 * 4));
            }
#pragma unroll
            for (int i = 0; i < 4; i++) {
                int slot = i * NTHR + tid;
                int row = slot >> 5, c4 = slot & 31;
                *(float4*)(hsf + row * B_ + c4 * 4) = pf[i];
            }

            ulonglong2 acc[8][2];
#pragma unroll
            for (int ib = 0; ib < 8; ib++)
#pragma unroll
                for (int jj = 0; jj < 2; jj++) { acc[ib][jj].x = 0ull; acc[ib][jj].y = 0ull; }

            for (int kc = 0; kc < NCHUNK; kc++) {
                if (kc + 1 < NCHUNK) {
#pragma unroll
                    for (int i = 0; i < 4; i++) {
                        int slot = i * NTHR + tid;
                        int row = slot >> 5, c4 = slot & 31;
                        pf[i] = __ldcg((const float4*)(hsrc + ((kc + 1) * BK + row) * B_ + c4 * 4));
                    }
                }
                __syncthreads();
                if (kc + 1 < NCHUNK) {
                    float* hb = hsf + ((kc + 1) & 1) * (BK * B_);
#pragma unroll
                    for (int i = 0; i < 4; i++) {
                        int slot = i * NTHR + tid;
                        int row = slot >> 5, c4 = slot & 31;
                        *(float4*)(hb + row * B_ + c4 * 4) = pf[i];
                    }
                }
                const float* hb = hsf + (kc & 1) * (BK * B_);
#pragma unroll
                for (int kk = 0; kk < BK; kk++) {
                    const float* hr = hb + kk * B_ + bg * 8;
                    float4 h0 = *(const float4*)hr;
                    float4 h1 = *(const float4*)(hr + 4);
                    const ulonglong2* wr = (const ulonglong2*)(ws + (kc * BK + kk) * JP_CTA + jg * 4);
                    ulonglong2 w0 = wr[0];
                    ulonglong2 w1 = wr[1];
                    unsigned long long d0 = dup2(h0.x), d1 = dup2(h0.y), d2 = dup2(h0.z), d3 = dup2(h0.w);
                    unsigned long long d4 = dup2(h1.x), d5 = dup2(h1.y), d6 = dup2(h1.z), d7 = dup2(h1.w);
                    FMA2(acc[0][0].x, d0, w0.x); FMA2(acc[0][0].y, d0, w0.y); FMA2(acc[0][1].x, d0, w1.x); FMA2(acc[0][1].y, d0, w1.y);
                    FMA2(acc[1][0].x, d1, w0.x); FMA2(acc[1][0].y, d1, w0.y); FMA2(acc[1][1].x, d1, w1.x); FMA2(acc[1][1].y, d1, w1.y);
                    FMA2(acc[2][0].x, d2, w0.x); FMA2(acc[2][0].y, d2, w0.y); FMA2(acc[2][1].x, d2, w1.x); FMA2(acc[2][1].y, d2, w1.y);
                    FMA2(acc[3][0].x, d3, w0.x); FMA2(acc[3][0].y, d3, w0.y); FMA2(acc[3][1].x, d3, w1.x); FMA2(acc[3][1].y, d3, w1.y);
                    FMA2(acc[4][0].x, d4, w0.x); FMA2(acc[4][0].y, d4, w0.y); FMA2(acc[4][1].x, d4, w1.x); FMA2(acc[4][1].y, d4, w1.y);
                    FMA2(acc[5][0].x, d5, w0.x); FMA2(acc[5][0].y, d5, w0.y); FMA2(acc[5][1].x, d5, w1.x); FMA2(acc[5][1].y, d5, w1.y);
                    FMA2(acc[6][0].x, d6, w0.x); FMA2(acc[6][0].y, d6, w0.y); FMA2(acc[6][1].x, d6, w1.x); FMA2(acc[6][1].y, d6, w1.y);
                    FMA2(acc[7][0].x, d7, w0.x); FMA2(acc[7][0].y, d7, w0.y); FMA2(acc[7][1].x, d7, w1.x); FMA2(acc[7][1].y, d7, w1.y);
                }
            }

            // ---- publish partials into step-parity slab ----
            unsigned long long* mypart = g_part + (size_t)(t & 1) * PARTBUF + (size_t)bid * OUTS_CTA;
#pragma unroll
            for (int ib = 0; ib < 8; ib++) {
                int b = bg * 8 + ib;
#pragma unroll
                for (int jj = 0; jj < 2; jj++)
                    *(ulonglong2*)(mypart + b * JP_CTA + jg * 4 + jj * 2) = acc[ib][jj];
            }
            __threadfence();
            __syncthreads();
            if (tid == 0) {
                if (isDec) atomicAdd(&g_decc[ks], 1u);   // hidden k-slice consumed
                atomicAdd(&g_flag[jt], 1u);
                unsigned target = (unsigned)KSPLIT * (unsigned)(t + 1);
                while (((volatile unsigned*)g_flag)[jt] < target) __nanosleep(20);
                if (!isDec && t >= 2) {                  // dec reader of buffer (t+1)%3 done?
                    unsigned dtarget = (unsigned)(t - 1);
                    while (((volatile unsigned*)g_decc)[jt >> 1] < dtarget) __nanosleep(20);
                }
                __threadfence();
            }
            __syncthreads();

            // ---- combine 16 k-slots + fused epilogue ----
            float R[2] = {0, 0}, F[2] = {0, 0};
            const unsigned long long* gp = g_part + (size_t)(t & 1) * PARTBUF +
                                           (size_t)(jt * KSPLIT) * OUTS_CTA + bloc * JP_CTA + jpb;
#pragma unroll
            for (int k2 = 0; k2 < KSPLIT; k2++) {
                uint4 q = __ldcg((const uint4*)(gp + (size_t)k2 * OUTS_CTA));
                R[0] += __uint_as_float(q.x); F[0] += __uint_as_float(q.y);
                R[1] += __uint_as_float(q.z); F[1] += __uint_as_float(q.w);
            }

            if (!isDec) {
                int hg0 = j0 + jpb;
                float2 e  = __ldcg((const float2*)(g_enc + (size_t)t * (B_ * NH) + bloc * NH + hg0));
                float2 ho = __ldcg((const float2*)(g_hidB[cur] + bloc * NH + hg0));
                const float ev[2]  = {e.x, e.y};
                const float hov[2] = {ho.x, ho.y};
                float hv[2];
#pragma unroll
                for (int i = 0; i < 2; i++) {
                    float f = 1.0f / (1.0f + __expf(-F[i]));
                    float s = ev[i] + R[i];
                    float hn = s / (1.0f + fabsf(s));
                    hv[i] = (1.0f - f) * hov[i] + f * hn;
                }
                *(float2*)(g_hidB[nxt] + bloc * NH + hg0) = make_float2(hv[0], hv[1]);
                g_hidT[nxt][(hg0 + 0) * B_ + bloc] = hv[0];
                g_hidT[nxt][(hg0 + 1) * B_ + bloc] = hv[1];

                // ---- signal: this tile's hidden share for step t+1 is ready ----
                __threadfence();
                __syncthreads();
                if (tid == 0) atomicAdd(&g_done[jt], 1u);
            } else if (t >= 1) {
                // pairs m=jpb, jpb+1 -> out cols 2*jpb .. 2*jpb+3
                float* op = out + (size_t)(t - 1) * (B_ * NO) + bloc * NO + jpb * 2;
                *(float2*)op       = make_float2(R[0] + db01.x, F[0] + db01.y);
                *(float2*)(op + 2) = make_float2(R[1] + db23.x, F[1] + db23.y);
            }
        }

        if (t == T_) break;
        cur = nxt;
    }

    // ---- final hidden copy: each rec CTA copies its tile's share ----
    if (writeHidden && !isDec) {
        if (tid == 0) {
            unsigned target = (unsigned)KSPLIT * (unsigned)T_;
            while (((volatile unsigned*)g_done)[jt] < target) __nanosleep(20);
            __threadfence();
        }
        __syncthreads();
        int b = ks * 8 + (tid >> 4);
        int h = jt * 32 + (tid & 15) * 2;
        float2 hv = *(const float2*)(g_hidB[cur] + b * NH + h);
        *(float2*)(out + (size_t)T_ * B_ * NO + (size_t)b * NH + h) = hv;
    }
}

// --------------------------------------------------------------------------------
extern "C" void kernel_launch(void* const* d_in, const int* in_sizes, int n_in,
                              void* d_out, int out_size) {
    const float* x       = (const float*)d_in[0];
    const float* enc_w   = (const float*)d_in[1];
    const float* enc_b   = (const float*)d_in[2];
    const float* rec_w   = (const float*)d_in[3];
    const float* fgt_w   = (const float*)d_in[4];
    const float* dec_w   = (const float*)d_in[5];
    const float* dec_b   = (const float*)d_in[6];
    const float* hinit_w = (const float*)d_in[7];
    const float* hinit_b = (const float*)d_in[8];
    float* out = (float*)d_out;

    reset_kernel<<<1, 64>>>();
    init_hidden_kernel<<<(B_ * NH + 255) / 256, 256>>>(hinit_w, hinit_b);

    dim3 eg(T_ * B_ / 32, NH / 64);
    enc_kernel<<<eg, 256>>>(x, enc_w, enc_b);

    cudaFuncSetAttribute(persist_kernel, cudaFuncAttributeMaxDynamicSharedMemorySize,
                         SMEM_BYTES);
    int writeHidden = (out_size >= T_ * B_ * NO + B_ * NH) ? 1 : 0;
    persist_kernel<<<NCTA, NTHR, SMEM_BYTES>>>(rec_w, fgt_w, dec_w, dec_b, out, writeHidden);
}

// round 13
// speedup vs baseline: 1.5516x; 1.5516x over previous
#include <cuda_runtime.h>
#include <cuda_bf16.h>
#include <math.h>

#define B_   128
#define T_   512
#define NI   64
#define NH   1024
#define NO   64

#define NCTA  132            // 2 b-halves x (64 rec + 2 dec); 1 CTA/SM
#define NTHR  256
#define SM_A  0              // A tiles: 2 slots x 2 splits x 16KB = 64KB
#define SM_B  65536          // B tiles: 2 splits x 64KB = 128KB
#define SMEM_BYTES 196608

// ---------------- scratch ------------------------------------------------------
__device__ float g_enc[(size_t)T_ * B_ * NH];              // [t][b][h] fp32
__device__ uint4 g_hbf[3ull * 2 * B_ * NH / 8];            // [buf][split][b][h] bf16
__device__ unsigned g_done[2];
__device__ unsigned g_decc[2];

// ---------------- helpers ------------------------------------------------------
__device__ __forceinline__ unsigned smem_u32(const void* p) {
    unsigned a;
    asm("{ .reg .u64 t; cvta.to.shared.u64 t, %1; cvt.u32.u64 %0, t; }" : "=r"(a) : "l"(p));
    return a;
}
__device__ __forceinline__ void ldsm_x4(unsigned r[4], unsigned addr) {
    asm volatile("ldmatrix.sync.aligned.m8n8.x4.shared.b16 {%0,%1,%2,%3}, [%4];"
                 : "=r"(r[0]), "=r"(r[1]), "=r"(r[2]), "=r"(r[3]) : "r"(addr));
}
__device__ __forceinline__ void ldsm_x4t(unsigned r[4], unsigned addr) {
    asm volatile("ldmatrix.sync.aligned.m8n8.x4.trans.shared.b16 {%0,%1,%2,%3}, [%4];"
                 : "=r"(r[0]), "=r"(r[1]), "=r"(r[2]), "=r"(r[3]) : "r"(addr));
}
__device__ __forceinline__ void mma16816(float d[4], const unsigned a[4],
                                         unsigned b0, unsigned b1) {
    asm volatile(
        "mma.sync.aligned.m16n8k16.row.col.f32.bf16.bf16.f32 "
        "{%0,%1,%2,%3}, {%4,%5,%6,%7}, {%8,%9}, {%0,%1,%2,%3};"
        : "+f"(d[0]), "+f"(d[1]), "+f"(d[2]), "+f"(d[3])
        : "r"(a[0]), "r"(a[1]), "r"(a[2]), "r"(a[3]), "r"(b0), "r"(b1));
}
__device__ __forceinline__ void split_bf(float v, __nv_bfloat16& hi, __nv_bfloat16& lo) {
    hi = __float2bfloat16(v);
    lo = __float2bfloat16(v - __bfloat162float(hi));
}

// ---------------- reset + init --------------------------------------------------
__global__ void reset_kernel() {
    if (threadIdx.x < 2) { g_done[threadIdx.x] = 0; g_decc[threadIdx.x] = 0; }
}

__global__ void init_hidden_kernel(const float* __restrict__ hinit_w,
                                   const float* __restrict__ hinit_b) {
    int idx = blockIdx.x * blockDim.x + threadIdx.x;
    if (idx < B_ * NH) {
        int h = idx & (NH - 1);
        float v = hinit_w[h] + hinit_b[h];
        __nv_bfloat16 hi, lo;
        split_bf(v, hi, lo);
        __nv_bfloat16* hb = (__nv_bfloat16*)g_hbf;
        hb[idx] = hi;                // buf0 split0
        hb[B_ * NH + idx] = lo;      // buf0 split1
    }
}

// ---------------- encoder GEMM (one-shot), fp32 [t][b][h] ------------------------
__global__ void __launch_bounds__(256) enc_kernel(const float* __restrict__ x,
                                                  const float* __restrict__ enc_w,
                                                  const float* __restrict__ enc_b) {
    __shared__ float xs[32][NI + 1];
    __shared__ float ws[64][NI + 1];
    const int tid = threadIdx.x;
    const int tb0 = blockIdx.x * 32;
    const int h0  = blockIdx.y * 64;

    for (int i = tid; i < 32 * NI; i += 256) {
        int r = i >> 6, c = i & 63;
        int tb = tb0 + r;
        int t = tb >> 7, b = tb & 127;
        xs[r][c] = x[(size_t)b * (T_ * NI) + t * NI + c];
    }
    for (int i = tid; i < 64 * NI; i += 256) {
        int r = i >> 6, c = i & 63;
        ws[r][c] = enc_w[(h0 + r) * NI + c];
    }
    __syncthreads();

    const int rg = tid & 7;
    const int hg = tid >> 3;
    float acc[4][2] = {};
#pragma unroll
    for (int k = 0; k < NI; k++) {
        float w0 = ws[hg * 2 + 0][k];
        float w1 = ws[hg * 2 + 1][k];
#pragma unroll
        for (int j = 0; j < 4; j++) {
            float xv = xs[rg * 4 + j][k];
            acc[j][0] += xv * w0;
            acc[j][1] += xv * w1;
        }
    }
#pragma unroll
    for (int j = 0; j < 4; j++) {
        int tb = tb0 + rg * 4 + j;
#pragma unroll
        for (int q = 0; q < 2; q++) {
            int h = h0 + hg * 2 + q;
            g_enc[(size_t)tb * NH + h] = acc[j][q] + enc_b[h];
        }
    }
}

// ---------------- persistent mma.sync recurrent kernel ---------------------------
// CTA: jc = bid>>1 (0..65), bh = bid&1 (b-half).
//   jc<64: rec tile, h cols jc*16..+15; B cols interleaved (R0,F0,...,R15,F15).
//   jc>=64: dec tile d=jc-64, out cols d*32..+31.
// Each CTA: D[64b x 32c] over full K=1024, split-bf16 3-term mma.sync, regs accum.
__global__ void __launch_bounds__(NTHR) persist_kernel(const float* __restrict__ rec_w,
                                                       const float* __restrict__ fgt_w,
                                                       const float* __restrict__ dec_w,
                                                       const float* __restrict__ dec_b,
                                                       const float* __restrict__ hinit_w,
                                                       const float* __restrict__ hinit_b,
                                                       float* __restrict__ out,
                                                       int writeHidden) {
    extern __shared__ __align__(128) char smem[];
    const unsigned sbase = smem_u32(smem);
    const int tid  = threadIdx.x;
    const int lane = tid & 31;
    const int wid  = tid >> 5;
    const int bid  = blockIdx.x;
    const int jc   = bid >> 1;
    const int bh   = bid & 1;
    const bool isDec = (jc >= 64);
    const int h0   = jc * 16;
    const int oc0  = (jc - 64) * 32;

    const int mt = wid & 3;          // m16 tile (rows mt*16.. within b-half)
    const int nh = wid >> 2;         // n16 half (ntiles 2nh, 2nh+1)
    const int matid   = lane >> 3;   // ldmatrix mat index
    const int r8      = lane & 7;
    const int khalf_l = lane >> 4;   // = matid>>1

    // ---- build resident B tiles (split bf16; mats: 8 k-rows x 8 n-cols) ----
    for (int i = tid; i < 32 * NH; i += NTHR) {
        int col = i >> 10, k = i & 1023;
        float w;
        if (!isDec) w = (col & 1) ? fgt_w[(h0 + (col >> 1)) * NH + k]
                                  : rec_w[(h0 + (col >> 1)) * NH + k];
        else        w = dec_w[(oc0 + col) * NH + k];
        __nv_bfloat16 hi, lo;
        split_bf(w, hi, lo);
        unsigned unit = (unsigned)((k >> 4) * 8 + (col >> 3) * 2 + ((k >> 3) & 1));
        unsigned off  = unit * 128 + (k & 7) * 16 + (col & 7) * 2;
        *(__nv_bfloat16*)(smem + SM_B + off) = hi;
        *(__nv_bfloat16*)(smem + SM_B + 65536 + off) = lo;
    }
    __syncthreads();

    // ---- per-thread epilogue ownership ----
    const int rowA = bh * 64 + mt * 16 + (lane >> 2);   // global b
    const int rowB = rowA + 8;
    const int hl0  = (2 * nh) * 4 + (lane & 3);         // local h (rec) / col base (dec)
    const int hl1  = (2 * nh + 1) * 4 + (lane & 3);
    float hold[4];
    if (!isDec) {
        hold[0] = __ldg(hinit_w + h0 + hl0) + __ldg(hinit_b + h0 + hl0);
        hold[1] = hold[0];
        hold[2] = __ldg(hinit_w + h0 + hl1) + __ldg(hinit_b + h0 + hl1);
        hold[3] = hold[2];
    }
    float db[4] = {0, 0, 0, 0};
    if (isDec) {
        int c0 = oc0 + (2 * nh) * 8 + 2 * (lane & 3);
        int c1 = oc0 + (2 * nh + 1) * 8 + 2 * (lane & 3);
        db[0] = __ldg(dec_b + c0); db[1] = __ldg(dec_b + c0 + 1);
        db[2] = __ldg(dec_b + c1); db[3] = __ldg(dec_b + c1 + 1);
    }

    const __nv_bfloat16* hbf = (const __nv_bfloat16*)g_hbf;

    for (int t = 0; t <= T_; t++) {
        const bool work = isDec || (t < T_);
        if (work) {
            const int cur = t % 3, nxtb = (t + 1) % 3;

            // ---- wait: all 64 rec producers of this b-half finished step t-1 ----
            if (tid == 0 && t > 0) {
                unsigned target = 64u * (unsigned)t;
                while (*(volatile unsigned*)&g_done[bh] < target) __nanosleep(20);
                __threadfence();
            }
            __syncthreads();

            float d0[4] = {0, 0, 0, 0};
            float d1[4] = {0, 0, 0, 0};
            const __nv_bfloat16* hb = hbf + (size_t)cur * 2 * B_ * NH;

            // ---- prologue: stage chunk 0 (K 0..127, both splits) ----
            uint4 pf[8];
#pragma unroll
            for (int i = 0; i < 8; i++) {
                int u = tid + i * NTHR;
                int sp = u >> 10, v = u & 1023, r = v >> 4, ku = v & 15;
                pf[i] = __ldcg((const uint4*)(hb + (size_t)sp * B_ * NH +
                                              (size_t)(bh * 64 + r) * NH + ku * 8));
            }
#pragma unroll
            for (int i = 0; i < 8; i++) {
                int u = tid + i * NTHR;
                int sp = u >> 10, v = u & 1023, r = v >> 4, ku = v & 15;
                unsigned unit = (unsigned)(((ku >> 1) * 4 + (r >> 4)) * 4 + (ku & 1) * 2 + ((r >> 3) & 1));
                unsigned slot = (unsigned)((r & 7) ^ (ku & 7));
                *(uint4*)(smem + SM_A + sp * 16384 + unit * 128 + slot * 16) = pf[i];
            }
            __syncthreads();

            for (int kc = 0; kc < 8; kc++) {
                if (kc + 1 < 8) {
#pragma unroll
                    for (int i = 0; i < 8; i++) {
                        int u = tid + i * NTHR;
                        int sp = u >> 10, v = u & 1023, r = v >> 4, ku = v & 15;
                        pf[i] = __ldcg((const uint4*)(hb + (size_t)sp * B_ * NH +
                                                      (size_t)(bh * 64 + r) * NH +
                                                      (kc + 1) * 128 + ku * 8));
                    }
                }
                const int s = kc & 1;
                const unsigned aHi = sbase + SM_A + s * 32768;
                const unsigned aLo = aHi + 16384;
                const unsigned bHi = sbase + SM_B;
                const unsigned bLo = bHi + 65536;
#pragma unroll
                for (int kt8 = 0; kt8 < 8; kt8++) {
                    unsigned aoff = (unsigned)(((kt8 * 4 + mt) * 4 + matid) * 128 +
                                    ((r8 ^ ((2 * kt8 + khalf_l) & 7)) << 4));
                    unsigned boff = (unsigned)((((kc * 8 + kt8) * 8) + nh * 4 + matid) * 128 + r8 * 16);
                    unsigned ah[4], al[4], bhv[4], blv[4];
                    ldsm_x4(ah, aHi + aoff);
                    ldsm_x4(al, aLo + aoff);
                    ldsm_x4t(bhv, bHi + boff);
                    ldsm_x4t(blv, bLo + boff);
                    mma16816(d0, ah, bhv[0], bhv[1]);
                    mma16816(d1, ah, bhv[2], bhv[3]);
                    mma16816(d0, al, bhv[0], bhv[1]);
                    mma16816(d1, al, bhv[2], bhv[3]);
                    mma16816(d0, ah, blv[0], blv[1]);
                    mma16816(d1, ah, blv[2], blv[3]);
                }
                if (kc + 1 < 8) {
                    __syncthreads();
#pragma unroll
                    for (int i = 0; i < 8; i++) {
                        int u = tid + i * NTHR;
                        int sp = u >> 10, v = u & 1023, r = v >> 4, ku = v & 15;
                        unsigned unit = (unsigned)(((ku >> 1) * 4 + (r >> 4)) * 4 + (ku & 1) * 2 + ((r >> 3) & 1));
                        unsigned slot = (unsigned)((r & 7) ^ (ku & 7));
                        *(uint4*)(smem + SM_A + ((kc + 1) & 1) * 32768 + sp * 16384 +
                                  unit * 128 + slot * 16) = pf[i];
                    }
                    __syncthreads();
                }
            }

            // ---- dec-consumption guard / signal ----
            if (tid == 0) {
                if (isDec) {
                    atomicAdd(&g_decc[bh], 1u);
                } else if (t >= 2) {
                    unsigned dt = 2u * (unsigned)(t - 1);
                    while (*(volatile unsigned*)&g_decc[bh] < dt) __nanosleep(20);
                    __threadfence();
                }
            }
            __syncthreads();

            // ---- fused epilogue ----
            if (!isDec) {
                const float* ep = g_enc + (size_t)t * (B_ * NH);
                float ev[4];
                ev[0] = __ldcg(ep + (size_t)rowA * NH + h0 + hl0);
                ev[1] = __ldcg(ep + (size_t)rowB * NH + h0 + hl0);
                ev[2] = __ldcg(ep + (size_t)rowA * NH + h0 + hl1);
                ev[3] = __ldcg(ep + (size_t)rowB * NH + h0 + hl1);
                // d layout: d0 -> hl0: {R(rowA), F(rowA), R(rowB), F(rowB)}; d1 -> hl1
                float R[4] = {d0[0], d0[2], d1[0], d1[2]};
                float F[4] = {d0[1], d0[3], d1[1], d1[3]};
                __nv_bfloat16* hw = (__nv_bfloat16*)g_hbf + (size_t)nxtb * 2 * B_ * NH;
                const int rows[4] = {rowA, rowB, rowA, rowB};
                const int hs[4] = {h0 + hl0, h0 + hl0, h0 + hl1, h0 + hl1};
#pragma unroll
                for (int i = 0; i < 4; i++) {
                    float f = 1.0f / (1.0f + __expf(-F[i]));
                    float sgn = ev[i] + R[i];
                    float hn = sgn / (1.0f + fabsf(sgn));
                    float hv = (1.0f - f) * hold[i] + f * hn;
                    hold[i] = hv;
                    __nv_bfloat16 hi, lo;
                    split_bf(hv, hi, lo);
                    size_t off = (size_t)rows[i] * NH + hs[i];
                    hw[off] = hi;
                    hw[(size_t)B_ * NH + off] = lo;
                }
                __threadfence();
                __syncthreads();
                if (tid == 0) atomicAdd(&g_done[bh], 1u);
            } else if (t >= 1) {
                float* op = out + (size_t)(t - 1) * (B_ * NO);
                int c0 = oc0 + (2 * nh) * 8 + 2 * (lane & 3);
                int c1 = oc0 + (2 * nh + 1) * 8 + 2 * (lane & 3);
                *(float2*)(op + (size_t)rowA * NO + c0) = make_float2(d0[0] + db[0], d0[1] + db[1]);
                *(float2*)(op + (size_t)rowB * NO + c0) = make_float2(d0[2] + db[0], d0[3] + db[1]);
                *(float2*)(op + (size_t)rowA * NO + c1) = make_float2(d1[0] + db[2], d1[1] + db[3]);
                *(float2*)(op + (size_t)rowB * NO + c1) = make_float2(d1[2] + db[2], d1[3] + db[3]);
            }
        }
        if (t == T_) break;
    }

    // ---- final hidden -> out tail [b][h] (from registers) ----
    if (writeHidden && !isDec) {
        float* dst = out + (size_t)T_ * B_ * NO;
        dst[(size_t)rowA * NH + h0 + hl0] = hold[0];
        dst[(size_t)rowB * NH + h0 + hl0] = hold[1];
        dst[(size_t)rowA * NH + h0 + hl1] = hold[2];
        dst[(size_t)rowB * NH + h0 + hl1] = hold[3];
    }
}

// --------------------------------------------------------------------------------
extern "C" void kernel_launch(void* const* d_in, const int* in_sizes, int n_in,
                              void* d_out, int out_size) {
    const float* x       = (const float*)d_in[0];
    const float* enc_w   = (const float*)d_in[1];
    const float* enc_b   = (const float*)d_in[2];
    const float* rec_w   = (const float*)d_in[3];
    const float* fgt_w   = (const float*)d_in[4];
    const float* dec_w   = (const float*)d_in[5];
    const float* dec_b   = (const float*)d_in[6];
    const float* hinit_w = (const float*)d_in[7];
    const float* hinit_b = (const float*)d_in[8];
    float* out = (float*)d_out;

    reset_kernel<<<1, 32>>>();
    init_hidden_kernel<<<(B_ * NH + 255) / 256, 256>>>(hinit_w, hinit_b);

    dim3 eg(T_ * B_ / 32, NH / 64);
    enc_kernel<<<eg, 256>>>(x, enc_w, enc_b);

    cudaFuncSetAttribute(persist_kernel, cudaFuncAttributeMaxDynamicSharedMemorySize,
                         SMEM_BYTES);
    int writeHidden = (out_size >= T_ * B_ * NO + B_ * NH) ? 1 : 0;
    persist_kernel<<<NCTA, NTHR, SMEM_BYTES>>>(rec_w, fgt_w, dec_w, dec_b,
                                               hinit_w, hinit_b, out, writeHidden);
}

// round 14
// speedup vs baseline: 1.6196x; 1.0438x over previous
#include <cuda_runtime.h>
#include <cuda_bf16.h>
#include <math.h>

#define B_   128
#define T_   512
#define NI   64
#define NH   1024
#define NO   64

#define NCTA  132            // 2 b-halves x (64 rec + 2 dec); 1 CTA/SM
#define NTHR  256
#define SM_A  0              // A tiles: 2 slots x 2 splits x 16KB = 64KB
#define SM_B  65536          // B tiles: 2 splits x 64KB = 128KB
#define SMEM_BYTES 196608

// ---------------- scratch ------------------------------------------------------
__device__ float g_enc[(size_t)T_ * B_ * NH];              // [t][b][h] fp32
__device__ uint4 g_hbf[3ull * 2 * B_ * NH / 8];            // [buf][split][b][h] bf16
__device__ unsigned g_done[2];
__device__ unsigned g_decc[2];

// ---------------- helpers ------------------------------------------------------
__device__ __forceinline__ unsigned smem_u32(const void* p) {
    unsigned a;
    asm("{ .reg .u64 t; cvta.to.shared.u64 t, %1; cvt.u32.u64 %0, t; }" : "=r"(a) : "l"(p));
    return a;
}
__device__ __forceinline__ void ldsm_x4(unsigned r[4], unsigned addr) {
    asm volatile("ldmatrix.sync.aligned.m8n8.x4.shared.b16 {%0,%1,%2,%3}, [%4];"
                 : "=r"(r[0]), "=r"(r[1]), "=r"(r[2]), "=r"(r[3]) : "r"(addr));
}
__device__ __forceinline__ void ldsm_x4t(unsigned r[4], unsigned addr) {
    asm volatile("ldmatrix.sync.aligned.m8n8.x4.trans.shared.b16 {%0,%1,%2,%3}, [%4];"
                 : "=r"(r[0]), "=r"(r[1]), "=r"(r[2]), "=r"(r[3]) : "r"(addr));
}
__device__ __forceinline__ void mma16816(float d[4], const unsigned a[4],
                                         unsigned b0, unsigned b1) {
    asm volatile(
        "mma.sync.aligned.m16n8k16.row.col.f32.bf16.bf16.f32 "
        "{%0,%1,%2,%3}, {%4,%5,%6,%7}, {%8,%9}, {%0,%1,%2,%3};"
        : "+f"(d[0]), "+f"(d[1]), "+f"(d[2]), "+f"(d[3])
        : "r"(a[0]), "r"(a[1]), "r"(a[2]), "r"(a[3]), "r"(b0), "r"(b1));
}
__device__ __forceinline__ void split_bf(float v, __nv_bfloat16& hi, __nv_bfloat16& lo) {
    hi = __float2bfloat16(v);
    lo = __float2bfloat16(v - __bfloat162float(hi));
}

// ---------------- reset + init --------------------------------------------------
__global__ void reset_kernel() {
    if (threadIdx.x < 2) { g_done[threadIdx.x] = 0; g_decc[threadIdx.x] = 0; }
}

__global__ void init_hidden_kernel(const float* __restrict__ hinit_w,
                                   const float* __restrict__ hinit_b) {
    int idx = blockIdx.x * blockDim.x + threadIdx.x;
    if (idx < B_ * NH) {
        int h = idx & (NH - 1);
        float v = hinit_w[h] + hinit_b[h];
        __nv_bfloat16 hi, lo;
        split_bf(v, hi, lo);
        __nv_bfloat16* hb = (__nv_bfloat16*)g_hbf;
        hb[idx] = hi;                // buf0 split0
        hb[B_ * NH + idx] = lo;      // buf0 split1
    }
}

// ---------------- encoder GEMM (one-shot), fp32 [t][b][h] ------------------------
__global__ void __launch_bounds__(256) enc_kernel(const float* __restrict__ x,
                                                  const float* __restrict__ enc_w,
                                                  const float* __restrict__ enc_b) {
    __shared__ float xs[32][NI + 1];
    __shared__ float ws[64][NI + 1];
    const int tid = threadIdx.x;
    const int tb0 = blockIdx.x * 32;
    const int h0  = blockIdx.y * 64;

    for (int i = tid; i < 32 * NI; i += 256) {
        int r = i >> 6, c = i & 63;
        int tb = tb0 + r;
        int t = tb >> 7, b = tb & 127;
        xs[r][c] = x[(size_t)b * (T_ * NI) + t * NI + c];
    }
    for (int i = tid; i < 64 * NI; i += 256) {
        int r = i >> 6, c = i & 63;
        ws[r][c] = enc_w[(h0 + r) * NI + c];
    }
    __syncthreads();

    const int rg = tid & 7;
    const int hg = tid >> 3;
    float acc[4][2] = {};
#pragma unroll
    for (int k = 0; k < NI; k++) {
        float w0 = ws[hg * 2 + 0][k];
        float w1 = ws[hg * 2 + 1][k];
#pragma unroll
        for (int j = 0; j < 4; j++) {
            float xv = xs[rg * 4 + j][k];
            acc[j][0] += xv * w0;
            acc[j][1] += xv * w1;
        }
    }
#pragma unroll
    for (int j = 0; j < 4; j++) {
        int tb = tb0 + rg * 4 + j;
#pragma unroll
        for (int q = 0; q < 2; q++) {
            int h = h0 + hg * 2 + q;
            g_enc[(size_t)tb * NH + h] = acc[j][q] + enc_b[h];
        }
    }
}

// ---------------- persistent mma.sync recurrent kernel ---------------------------
// CTA: jc = bid>>1 (0..65), bh = bid&1 (b-half).
//   jc<64: rec tile, h cols jc*16..+15; B cols interleaved (R0,F0,...,R15,F15).
//   jc>=64: dec tile d=jc-64, out cols d*32..+31.
// Each CTA: D[64b x 32c] over full K=1024, split-bf16 3-term mma.sync.
// Each split-term gets its OWN accumulator set -> 6 independent MMA chains/warp.
__global__ void __launch_bounds__(NTHR) persist_kernel(const float* __restrict__ rec_w,
                                                       const float* __restrict__ fgt_w,
                                                       const float* __restrict__ dec_w,
                                                       const float* __restrict__ dec_b,
                                                       const float* __restrict__ hinit_w,
                                                       const float* __restrict__ hinit_b,
                                                       float* __restrict__ out,
                                                       int writeHidden) {
    extern __shared__ __align__(128) char smem[];
    const unsigned sbase = smem_u32(smem);
    const int tid  = threadIdx.x;
    const int lane = tid & 31;
    const int wid  = tid >> 5;
    const int bid  = blockIdx.x;
    const int jc   = bid >> 1;
    const int bh   = bid & 1;
    const bool isDec = (jc >= 64);
    const int h0   = jc * 16;
    const int oc0  = (jc - 64) * 32;

    const int mt = wid & 3;          // m16 tile (rows mt*16.. within b-half)
    const int nh = wid >> 2;         // n16 half (ntiles 2nh, 2nh+1)
    const int matid   = lane >> 3;   // ldmatrix mat index
    const int r8      = lane & 7;
    const int khalf_l = lane >> 4;

    // ---- build resident B tiles (split bf16; mats: 8 k-rows x 8 n-cols) ----
    for (int i = tid; i < 32 * NH; i += NTHR) {
        int col = i >> 10, k = i & 1023;
        float w;
        if (!isDec) w = (col & 1) ? fgt_w[(h0 + (col >> 1)) * NH + k]
                                  : rec_w[(h0 + (col >> 1)) * NH + k];
        else        w = dec_w[(oc0 + col) * NH + k];
        __nv_bfloat16 hi, lo;
        split_bf(w, hi, lo);
        unsigned unit = (unsigned)((k >> 4) * 8 + (col >> 3) * 2 + ((k >> 3) & 1));
        unsigned off  = unit * 128 + (k & 7) * 16 + (col & 7) * 2;
        *(__nv_bfloat16*)(smem + SM_B + off) = hi;
        *(__nv_bfloat16*)(smem + SM_B + 65536 + off) = lo;
    }
    __syncthreads();

    // ---- per-thread epilogue ownership ----
    const int rowA = bh * 64 + mt * 16 + (lane >> 2);   // global b
    const int rowB = rowA + 8;
    const int hl0  = (2 * nh) * 4 + (lane & 3);         // local h (rec) / col base (dec)
    const int hl1  = (2 * nh + 1) * 4 + (lane & 3);
    float hold[4];
    if (!isDec) {
        hold[0] = __ldg(hinit_w + h0 + hl0) + __ldg(hinit_b + h0 + hl0);
        hold[1] = hold[0];
        hold[2] = __ldg(hinit_w + h0 + hl1) + __ldg(hinit_b + h0 + hl1);
        hold[3] = hold[2];
    }
    float db[4] = {0, 0, 0, 0};
    if (isDec) {
        int c0 = oc0 + (2 * nh) * 8 + 2 * (lane & 3);
        int c1 = oc0 + (2 * nh + 1) * 8 + 2 * (lane & 3);
        db[0] = __ldg(dec_b + c0); db[1] = __ldg(dec_b + c0 + 1);
        db[2] = __ldg(dec_b + c1); db[3] = __ldg(dec_b + c1 + 1);
    }

    const __nv_bfloat16* hbf = (const __nv_bfloat16*)g_hbf;

    for (int t = 0; t <= T_; t++) {
        const bool work = isDec || (t < T_);
        if (work) {
            const int cur = t % 3, nxtb = (t + 1) % 3;

            // ---- wait: all 64 rec producers of this b-half finished step t-1 ----
            if (tid == 0 && t > 0) {
                unsigned target = 64u * (unsigned)t;
                while (*(volatile unsigned*)&g_done[bh] < target) __nanosleep(20);
                __threadfence();
            }
            __syncthreads();

            // 6 independent accumulator chains
            float d0h[4] = {0, 0, 0, 0}, d0l[4] = {0, 0, 0, 0}, d0w[4] = {0, 0, 0, 0};
            float d1h[4] = {0, 0, 0, 0}, d1l[4] = {0, 0, 0, 0}, d1w[4] = {0, 0, 0, 0};
            const __nv_bfloat16* hb = hbf + (size_t)cur * 2 * B_ * NH;

            // ---- prologue: stage chunk 0 (K 0..127, both splits) ----
            uint4 pf[8];
#pragma unroll
            for (int i = 0; i < 8; i++) {
                int u = tid + i * NTHR;
                int sp = u >> 10, v = u & 1023, r = v >> 4, ku = v & 15;
                pf[i] = __ldcg((const uint4*)(hb + (size_t)sp * B_ * NH +
                                              (size_t)(bh * 64 + r) * NH + ku * 8));
            }
#pragma unroll
            for (int i = 0; i < 8; i++) {
                int u = tid + i * NTHR;
                int sp = u >> 10, v = u & 1023, r = v >> 4, ku = v & 15;
                unsigned unit = (unsigned)(((ku >> 1) * 4 + (r >> 4)) * 4 + (ku & 1) * 2 + ((r >> 3) & 1));
                unsigned slot = (unsigned)((r & 7) ^ (ku & 7));
                *(uint4*)(smem + SM_A + sp * 16384 + unit * 128 + slot * 16) = pf[i];
            }
            __syncthreads();

            for (int kc = 0; kc < 8; kc++) {
                if (kc + 1 < 8) {
#pragma unroll
                    for (int i = 0; i < 8; i++) {
                        int u = tid + i * NTHR;
                        int sp = u >> 10, v = u & 1023, r = v >> 4, ku = v & 15;
                        pf[i] = __ldcg((const uint4*)(hb + (size_t)sp * B_ * NH +
                                                      (size_t)(bh * 64 + r) * NH +
                                                      (kc + 1) * 128 + ku * 8));
                    }
                }
                const int s = kc & 1;
                const unsigned aHi = sbase + SM_A + s * 32768;
                const unsigned aLo = aHi + 16384;
                const unsigned bHi = sbase + SM_B;
                const unsigned bLo = bHi + 65536;
#pragma unroll
                for (int kt8 = 0; kt8 < 8; kt8++) {
                    unsigned aoff = (unsigned)(((kt8 * 4 + mt) * 4 + matid) * 128 +
                                    ((r8 ^ ((2 * kt8 + khalf_l) & 7)) << 4));
                    unsigned boff = (unsigned)((((kc * 8 + kt8) * 8) + nh * 4 + matid) * 128 + r8 * 16);
                    unsigned ah[4], al[4], bhv[4], blv[4];
                    ldsm_x4(ah, aHi + aoff);
                    ldsm_x4(al, aLo + aoff);
                    ldsm_x4t(bhv, bHi + boff);
                    ldsm_x4t(blv, bLo + boff);
                    mma16816(d0h, ah, bhv[0], bhv[1]);
                    mma16816(d1h, ah, bhv[2], bhv[3]);
                    mma16816(d0l, al, bhv[0], bhv[1]);
                    mma16816(d1l, al, bhv[2], bhv[3]);
                    mma16816(d0w, ah, blv[0], blv[1]);
                    mma16816(d1w, ah, blv[2], blv[3]);
                }
                if (kc + 1 < 8) {
                    __syncthreads();
#pragma unroll
                    for (int i = 0; i < 8; i++) {
                        int u = tid + i * NTHR;
                        int sp = u >> 10, v = u & 1023, r = v >> 4, ku = v & 15;
                        unsigned unit = (unsigned)(((ku >> 1) * 4 + (r >> 4)) * 4 + (ku & 1) * 2 + ((r >> 3) & 1));
                        unsigned slot = (unsigned)((r & 7) ^ (ku & 7));
                        *(uint4*)(smem + SM_A + ((kc + 1) & 1) * 32768 + sp * 16384 +
                                  unit * 128 + slot * 16) = pf[i];
                    }
                    __syncthreads();
                }
            }

            // fold the 3 term-chains
            float d0[4], d1[4];
#pragma unroll
            for (int i = 0; i < 4; i++) {
                d0[i] = d0h[i] + d0l[i] + d0w[i];
                d1[i] = d1h[i] + d1l[i] + d1w[i];
            }

            // ---- dec-consumption guard / signal ----
            if (tid == 0) {
                if (isDec) {
                    atomicAdd(&g_decc[bh], 1u);
                } else if (t >= 2) {
                    unsigned dt = 2u * (unsigned)(t - 1);
                    while (*(volatile unsigned*)&g_decc[bh] < dt) __nanosleep(20);
                    __threadfence();
                }
            }
            __syncthreads();

            // ---- fused epilogue ----
            if (!isDec) {
                const float* ep = g_enc + (size_t)t * (B_ * NH);
                float ev[4];
                ev[0] = __ldcg(ep + (size_t)rowA * NH + h0 + hl0);
                ev[1] = __ldcg(ep + (size_t)rowB * NH + h0 + hl0);
                ev[2] = __ldcg(ep + (size_t)rowA * NH + h0 + hl1);
                ev[3] = __ldcg(ep + (size_t)rowB * NH + h0 + hl1);
                float R[4] = {d0[0], d0[2], d1[0], d1[2]};
                float F[4] = {d0[1], d0[3], d1[1], d1[3]};
                __nv_bfloat16* hw = (__nv_bfloat16*)g_hbf + (size_t)nxtb * 2 * B_ * NH;
                const int rows[4] = {rowA, rowB, rowA, rowB};
                const int hs[4] = {h0 + hl0, h0 + hl0, h0 + hl1, h0 + hl1};
#pragma unroll
                for (int i = 0; i < 4; i++) {
                    float f = 1.0f / (1.0f + __expf(-F[i]));
                    float sgn = ev[i] + R[i];
                    float hn = sgn / (1.0f + fabsf(sgn));
                    float hv = (1.0f - f) * hold[i] + f * hn;
                    hold[i] = hv;
                    __nv_bfloat16 hi, lo;
                    split_bf(hv, hi, lo);
                    size_t off = (size_t)rows[i] * NH + hs[i];
                    hw[off] = hi;
                    hw[(size_t)B_ * NH + off] = lo;
                }
                __threadfence();
                __syncthreads();
                if (tid == 0) atomicAdd(&g_done[bh], 1u);
            } else if (t >= 1) {
                float* op = out + (size_t)(t - 1) * (B_ * NO);
                int c0 = oc0 + (2 * nh) * 8 + 2 * (lane & 3);
                int c1 = oc0 + (2 * nh + 1) * 8 + 2 * (lane & 3);
                *(float2*)(op + (size_t)rowA * NO + c0) = make_float2(d0[0] + db[0], d0[1] + db[1]);
                *(float2*)(op + (size_t)rowB * NO + c0) = make_float2(d0[2] + db[0], d0[3] + db[1]);
                *(float2*)(op + (size_t)rowA * NO + c1) = make_float2(d1[0] + db[2], d1[1] + db[3]);
                *(float2*)(op + (size_t)rowB * NO + c1) = make_float2(d1[2] + db[2], d1[3] + db[3]);
            }
        }
        if (t == T_) break;
    }

    // ---- final hidden -> out tail [b][h] (from registers) ----
    if (writeHidden && !isDec) {
        float* dst = out + (size_t)T_ * B_ * NO;
        dst[(size_t)rowA * NH + h0 + hl0] = hold[0];
        dst[(size_t)rowB * NH + h0 + hl0] = hold[1];
        dst[(size_t)rowA * NH + h0 + hl1] = hold[2];
        dst[(size_t)rowB * NH + h0 + hl1] = hold[3];
    }
}

// --------------------------------------------------------------------------------
extern "C" void kernel_launch(void* const* d_in, const int* in_sizes, int n_in,
                              void* d_out, int out_size) {
    const float* x       = (const float*)d_in[0];
    const float* enc_w   = (const float*)d_in[1];
    const float* enc_b   = (const float*)d_in[2];
    const float* rec_w   = (const float*)d_in[3];
    const float* fgt_w   = (const float*)d_in[4];
    const float* dec_w   = (const float*)d_in[5];
    const float* dec_b   = (const float*)d_in[6];
    const float* hinit_w = (const float*)d_in[7];
    const float* hinit_b = (const float*)d_in[8];
    float* out = (float*)d_out;

    reset_kernel<<<1, 32>>>();
    init_hidden_kernel<<<(B_ * NH + 255) / 256, 256>>>(hinit_w, hinit_b);

    dim3 eg(T_ * B_ / 32, NH / 64);
    enc_kernel<<<eg, 256>>>(x, enc_w, enc_b);

    cudaFuncSetAttribute(persist_kernel, cudaFuncAttributeMaxDynamicSharedMemorySize,
                         SMEM_BYTES);
    int writeHidden = (out_size >= T_ * B_ * NO + B_ * NH) ? 1 : 0;
    persist_kernel<<<NCTA, NTHR, SMEM_BYTES>>>(rec_w, fgt_w, dec_w, dec_b,
                                               hinit_w, hinit_b, out, writeHidden);
}

// round 15
// speedup vs baseline: 1.6398x; 1.0125x over previous
#include <cuda_runtime.h>
#include <cuda_bf16.h>
#include <math.h>

#define B_   128
#define T_   512
#define NI   64
#define NH   1024
#define NO   64

#define NCTA  132            // 2 b-halves x (64 rec + 2 dec); 1 CTA/SM
#define NTHR  256
#define BNH   (B_ * NH)

// SMEM: [0..131072) B build (init only) / [0..34816) P reduction (steps)
//       [131072..196608) A: 4 pairs x 2 slots x (hi 4KB + lo 4KB)
#define SM_B0 0
#define SM_A  131072
#define SMEM_BYTES 196608
#define PSTRIDE 34           // floats per b-row in P (136B, padded)

// ---------------- scratch ------------------------------------------------------
__device__ float g_enc[(size_t)T_ * B_ * NH];              // [t][b][h] fp32
__device__ uint4 g_hbf[3ull * 2 * B_ * NH / 8];            // [buf][split][b][h] bf16
__device__ unsigned g_done[2];
__device__ unsigned g_decc[2];

// ---------------- helpers ------------------------------------------------------
__device__ __forceinline__ unsigned smem_u32(const void* p) {
    unsigned a;
    asm("{ .reg .u64 t; cvta.to.shared.u64 t, %1; cvt.u32.u64 %0, t; }" : "=r"(a) : "l"(p));
    return a;
}
__device__ __forceinline__ void ldsm_x4(unsigned r[4], unsigned addr) {
    asm volatile("ldmatrix.sync.aligned.m8n8.x4.shared.b16 {%0,%1,%2,%3}, [%4];"
                 : "=r"(r[0]), "=r"(r[1]), "=r"(r[2]), "=r"(r[3]) : "r"(addr));
}
__device__ __forceinline__ void ldsm_x4t(unsigned r[4], unsigned addr) {
    asm volatile("ldmatrix.sync.aligned.m8n8.x4.trans.shared.b16 {%0,%1,%2,%3}, [%4];"
                 : "=r"(r[0]), "=r"(r[1]), "=r"(r[2]), "=r"(r[3]) : "r"(addr));
}
__device__ __forceinline__ void mma16816(float d[4], const unsigned a[4],
                                         unsigned b0, unsigned b1) {
    asm volatile(
        "mma.sync.aligned.m16n8k16.row.col.f32.bf16.bf16.f32 "
        "{%0,%1,%2,%3}, {%4,%5,%6,%7}, {%8,%9}, {%0,%1,%2,%3};"
        : "+f"(d[0]), "+f"(d[1]), "+f"(d[2]), "+f"(d[3])
        : "r"(a[0]), "r"(a[1]), "r"(a[2]), "r"(a[3]), "r"(b0), "r"(b1));
}
__device__ __forceinline__ void split_bf(float v, __nv_bfloat16& hi, __nv_bfloat16& lo) {
    hi = __float2bfloat16(v);
    lo = __float2bfloat16(v - __bfloat162float(hi));
}
#define PAIR_BAR(kq) asm volatile("bar.sync %0, 64;" :: "r"(1 + (kq)) : "memory")

// ---------------- reset + init --------------------------------------------------
__global__ void reset_kernel() {
    if (threadIdx.x < 2) { g_done[threadIdx.x] = 0; g_decc[threadIdx.x] = 0; }
}

__global__ void init_hidden_kernel(const float* __restrict__ hinit_w,
                                   const float* __restrict__ hinit_b) {
    int idx = blockIdx.x * blockDim.x + threadIdx.x;
    if (idx < B_ * NH) {
        int h = idx & (NH - 1);
        float v = hinit_w[h] + hinit_b[h];
        __nv_bfloat16 hi, lo;
        split_bf(v, hi, lo);
        __nv_bfloat16* hb = (__nv_bfloat16*)g_hbf;
        hb[idx] = hi;
        hb[B_ * NH + idx] = lo;
    }
}

// ---------------- encoder GEMM (one-shot), fp32 [t][b][h] ------------------------
__global__ void __launch_bounds__(256) enc_kernel(const float* __restrict__ x,
                                                  const float* __restrict__ enc_w,
                                                  const float* __restrict__ enc_b) {
    __shared__ float xs[32][NI + 1];
    __shared__ float ws[64][NI + 1];
    const int tid = threadIdx.x;
    const int tb0 = blockIdx.x * 32;
    const int h0  = blockIdx.y * 64;

    for (int i = tid; i < 32 * NI; i += 256) {
        int r = i >> 6, c = i & 63;
        int tb = tb0 + r;
        int t = tb >> 7, b = tb & 127;
        xs[r][c] = x[(size_t)b * (T_ * NI) + t * NI + c];
    }
    for (int i = tid; i < 64 * NI; i += 256) {
        int r = i >> 6, c = i & 63;
        ws[r][c] = enc_w[(h0 + r) * NI + c];
    }
    __syncthreads();

    const int rg = tid & 7;
    const int hg = tid >> 3;
    float acc[4][2] = {};
#pragma unroll
    for (int k = 0; k < NI; k++) {
        float w0 = ws[hg * 2 + 0][k];
        float w1 = ws[hg * 2 + 1][k];
#pragma unroll
        for (int j = 0; j < 4; j++) {
            float xv = xs[rg * 4 + j][k];
            acc[j][0] += xv * w0;
            acc[j][1] += xv * w1;
        }
    }
#pragma unroll
    for (int j = 0; j < 4; j++) {
        int tb = tb0 + rg * 4 + j;
#pragma unroll
        for (int q = 0; q < 2; q++) {
            int h = h0 + hg * 2 + q;
            g_enc[(size_t)tb * NH + h] = acc[j][q] + enc_b[h];
        }
    }
}

// ---------------- persistent mma.sync recurrent kernel ---------------------------
// CTA: jc = bid>>1 (0..65), bh = bid&1.
//   jc<64: rec tile, h cols jc*16..+15 (B cols interleaved R,F); jc>=64: dec tile.
// Warps: kq = wid>>1 (k-quarter of 256), nh = wid&1 (n16 half).
// B fragments (hi+lo) live in 128 registers per warp across all steps.
// A staged per-pair (k32 slots, double-buffered, named barriers). Per-step
// cross-kq reduction through smem P, then fused epilogue.
__global__ void __launch_bounds__(NTHR) persist_kernel(const float* __restrict__ rec_w,
                                                       const float* __restrict__ fgt_w,
                                                       const float* __restrict__ dec_w,
                                                       const float* __restrict__ dec_b,
                                                       const float* __restrict__ hinit_w,
                                                       const float* __restrict__ hinit_b,
                                                       float* __restrict__ out,
                                                       int writeHidden) {
    extern __shared__ __align__(128) char smem[];
    const unsigned sbase = smem_u32(smem);
    float* Pf = (float*)smem;                 // reduction region (offset 0)
    const int tid  = threadIdx.x;
    const int lane = tid & 31;
    const int wid  = tid >> 5;
    const int bid  = blockIdx.x;
    const int jc   = bid >> 1;
    const int bh   = bid & 1;
    const bool isDec = (jc >= 64);
    const int h0   = jc * 16;
    const int oc0  = (jc - 64) * 32;

    const int kq = wid >> 1;            // k-quarter 0..3
    const int nh = wid & 1;             // n16 half
    const int pairTid = tid & 63;
    const int matid   = lane >> 3;
    const int r8      = lane & 7;
    const int khalf_l = lane >> 4;

    // ---- build B mats in smem (temporary), then preload fragments to registers ----
    for (int i = tid; i < 32 * NH; i += NTHR) {
        int col = i >> 10, k = i & 1023;
        float w;
        if (!isDec) w = (col & 1) ? fgt_w[(h0 + (col >> 1)) * NH + k]
                                  : rec_w[(h0 + (col >> 1)) * NH + k];
        else        w = dec_w[(oc0 + col) * NH + k];
        __nv_bfloat16 hi, lo;
        split_bf(w, hi, lo);
        unsigned unit = (unsigned)((k >> 4) * 8 + (col >> 3) * 2 + ((k >> 3) & 1));
        unsigned off  = unit * 128 + (k & 7) * 16 + (col & 7) * 2;
        *(__nv_bfloat16*)(smem + SM_B0 + off) = hi;
        *(__nv_bfloat16*)(smem + SM_B0 + 65536 + off) = lo;
    }
    __syncthreads();

    unsigned bHf[16][4], bLf[16][4];
#pragma unroll
    for (int kk = 0; kk < 16; kk++) {
        unsigned boff = (unsigned)(((kq * 16 + kk) * 8 + nh * 4 + matid) * 128 + r8 * 16);
        ldsm_x4t(bHf[kk], sbase + SM_B0 + boff);
        ldsm_x4t(bLf[kk], sbase + SM_B0 + 65536 + boff);
    }
    __syncthreads();   // B smem now dead; region reused as P

    // ---- epilogue ownership: thread -> (b, 4 h-cols) ----
    const int eb  = tid >> 2;                 // local b 0..63
    const int ehl = (tid & 3) * 4;            // first of 4 owned h (local)
    const int gb  = bh * 64 + eb;             // global b
    float hold[4];
    if (!isDec) {
#pragma unroll
        for (int i = 0; i < 4; i++)
            hold[i] = __ldg(hinit_w + h0 + ehl + i) + __ldg(hinit_b + h0 + ehl + i);
    }
    float db[8];
    if (isDec) {
#pragma unroll
        for (int i = 0; i < 8; i++)
            db[i] = __ldg(dec_b + oc0 + ehl * 2 + i);
    }

    const __nv_bfloat16* hbf = (const __nv_bfloat16*)g_hbf;
    const unsigned aPair = sbase + SM_A + kq * 16384;

    for (int t = 0; t <= T_; t++) {
        const bool work = isDec || (t < T_);
        if (work) {
            const int cur = t % 3, nxtb = (t + 1) % 3;

            // ---- wait: all 64 rec producers of this b-half finished step t-1 ----
            if (tid == 0 && t > 0) {
                unsigned target = 64u * (unsigned)t;
                while (*(volatile unsigned*)&g_done[bh] < target) __nanosleep(20);
                __threadfence();
            }
            __syncthreads();

            const __nv_bfloat16* hb = hbf + (size_t)cur * 2 * BNH;

            // epilogue operand prefetch
            float4 e4;
            if (!isDec)
                e4 = __ldcg((const float4*)(g_enc + (size_t)t * BNH + (size_t)gb * NH + h0 + ehl));

            float acc[4][2][4];
#pragma unroll
            for (int m = 0; m < 4; m++)
#pragma unroll
                for (int g = 0; g < 2; g++)
#pragma unroll
                    for (int q = 0; q < 4; q++) acc[m][g][q] = 0.f;

            // ---- prologue: stage slot 0 (k32 subchunk 0 of this kq) ----
            {
                uint4 pf[8];
#pragma unroll
                for (int j = 0; j < 8; j++) {
                    int u = pairTid + j * 64;
                    int sp = u >> 8, v = u & 255, r = v >> 2, ku = v & 3;
                    pf[j] = __ldcg((const uint4*)(hb + (size_t)sp * BNH +
                                                  (size_t)(bh * 64 + r) * NH +
                                                  kq * 256 + ku * 8));
                }
#pragma unroll
                for (int j = 0; j < 8; j++) {
                    int u = pairTid + j * 64;
                    int sp = u >> 8, v = u & 255, r = v >> 2, ku = v & 3;
                    unsigned unit = (unsigned)(((ku >> 1) * 4 + (r >> 4)) * 4 + (ku & 1) * 2 + ((r >> 3) & 1));
                    unsigned xs = (unsigned)((r & 7) ^ ku);
                    *(uint4*)(smem + SM_A + kq * 16384 + sp * 4096 + unit * 128 + xs * 16) = pf[j];
                }
            }
            PAIR_BAR(kq);

#pragma unroll
            for (int sc = 0; sc < 8; sc++) {
                uint4 pf[8];
                if (sc + 1 < 8) {
#pragma unroll
                    for (int j = 0; j < 8; j++) {
                        int u = pairTid + j * 64;
                        int sp = u >> 8, v = u & 255, r = v >> 2, ku = v & 3;
                        pf[j] = __ldcg((const uint4*)(hb + (size_t)sp * BNH +
                                                      (size_t)(bh * 64 + r) * NH +
                                                      kq * 256 + (sc + 1) * 32 + ku * 8));
                    }
                }
                const unsigned aBase = aPair + (unsigned)(sc & 1) * 8192;
#pragma unroll
                for (int kl = 0; kl < 2; kl++) {
                    const int kk = sc * 2 + kl;
#pragma unroll
                    for (int mt = 0; mt < 4; mt++) {
                        unsigned aoff = (unsigned)(((kl * 4 + mt) * 4 + matid) * 128 +
                                        ((r8 ^ (2 * kl + khalf_l)) << 4));
                        unsigned ah[4], al[4];
                        ldsm_x4(ah, aBase + aoff);
                        ldsm_x4(al, aBase + 4096 + aoff);
                        mma16816(acc[mt][0], ah, bHf[kk][0], bHf[kk][1]);
                        mma16816(acc[mt][1], ah, bHf[kk][2], bHf[kk][3]);
                        mma16816(acc[mt][0], al, bHf[kk][0], bHf[kk][1]);
                        mma16816(acc[mt][1], al, bHf[kk][2], bHf[kk][3]);
                        mma16816(acc[mt][0], ah, bLf[kk][0], bLf[kk][1]);
                        mma16816(acc[mt][1], ah, bLf[kk][2], bLf[kk][3]);
                    }
                }
                if (sc + 1 < 8) {
#pragma unroll
                    for (int j = 0; j < 8; j++) {
                        int u = pairTid + j * 64;
                        int sp = u >> 8, v = u & 255, r = v >> 2, ku = v & 3;
                        unsigned unit = (unsigned)(((ku >> 1) * 4 + (r >> 4)) * 4 + (ku & 1) * 2 + ((r >> 3) & 1));
                        unsigned xs = (unsigned)((r & 7) ^ ku);
                        *(uint4*)(smem + SM_A + kq * 16384 + ((sc + 1) & 1) * 8192 +
                                  sp * 4096 + unit * 128 + xs * 16) = pf[j];
                    }
                    PAIR_BAR(kq);
                }
            }

            // ---- store partials into P[kq][b][col] ----
#pragma unroll
            for (int mt = 0; mt < 4; mt++) {
#pragma unroll
                for (int g = 0; g < 2; g++) {
                    int c = nh * 16 + g * 8 + 2 * (lane & 3);
                    int rA = mt * 16 + (lane >> 2);
                    float* p = Pf + kq * (64 * PSTRIDE) + rA * PSTRIDE + c;
                    *(float2*)p = make_float2(acc[mt][g][0], acc[mt][g][1]);
                    *(float2*)(p + 8 * PSTRIDE) = make_float2(acc[mt][g][2], acc[mt][g][3]);
                }
            }
            __syncthreads();

            // ---- reduce 4 kq + dec guard ----
            if (tid == 0) {
                if (isDec) {
                    atomicAdd(&g_decc[bh], 1u);
                } else if (t >= 2) {
                    unsigned dt = 2u * (unsigned)(t - 1);
                    while (*(volatile unsigned*)&g_decc[bh] < dt) __nanosleep(20);
                    __threadfence();
                }
            }

            float R[4], F[4];
#pragma unroll
            for (int i = 0; i < 4; i++) {
                float2 s = *(const float2*)(Pf + eb * PSTRIDE + 2 * (ehl + i));
                float2 s1 = *(const float2*)(Pf + 1 * (64 * PSTRIDE) + eb * PSTRIDE + 2 * (ehl + i));
                float2 s2 = *(const float2*)(Pf + 2 * (64 * PSTRIDE) + eb * PSTRIDE + 2 * (ehl + i));
                float2 s3 = *(const float2*)(Pf + 3 * (64 * PSTRIDE) + eb * PSTRIDE + 2 * (ehl + i));
                R[i] = s.x + s1.x + s2.x + s3.x;
                F[i] = s.y + s1.y + s2.y + s3.y;
            }

            // ---- fused epilogue ----
            if (!isDec) {
                const float ev[4] = {e4.x, e4.y, e4.z, e4.w};
                union { __nv_bfloat16 h[4]; uint2 v; } phi, plo;
#pragma unroll
                for (int i = 0; i < 4; i++) {
                    float f = 1.0f / (1.0f + __expf(-F[i]));
                    float sgn = ev[i] + R[i];
                    float hn = sgn / (1.0f + fabsf(sgn));
                    float hv = (1.0f - f) * hold[i] + f * hn;
                    hold[i] = hv;
                    split_bf(hv, phi.h[i], plo.h[i]);
                }
                __nv_bfloat16* hw = (__nv_bfloat16*)g_hbf + (size_t)nxtb * 2 * BNH +
                                    (size_t)gb * NH + h0 + ehl;
                *(uint2*)hw = phi.v;
                *(uint2*)(hw + BNH) = plo.v;
                __threadfence();
                __syncthreads();
                if (tid == 0) atomicAdd(&g_done[bh], 1u);
            } else if (t >= 1) {
                float* op = out + (size_t)(t - 1) * (B_ * NO) + (size_t)gb * NO + oc0 + ehl * 2;
                float4 v0 = make_float4(R[0] + db[0], F[0] + db[1], R[1] + db[2], F[1] + db[3]);
                float4 v1 = make_float4(R[2] + db[4], F[2] + db[5], R[3] + db[6], F[3] + db[7]);
                *(float4*)op = v0;
                *(float4*)(op + 4) = v1;
                __syncthreads();    // all warps done reading P before next step's STS
            } else {
                __syncthreads();
            }
        }
        if (t == T_) break;
    }

    // ---- final hidden -> out tail [b][h] (from registers) ----
    if (writeHidden && !isDec) {
        float* dst = out + (size_t)T_ * B_ * NO + (size_t)gb * NH + h0 + ehl;
        *(float4*)dst = make_float4(hold[0], hold[1], hold[2], hold[3]);
    }
}

// --------------------------------------------------------------------------------
extern "C" void kernel_launch(void* const* d_in, const int* in_sizes, int n_in,
                              void* d_out, int out_size) {
    const float* x       = (const float*)d_in[0];
    const float* enc_w   = (const float*)d_in[1];
    const float* enc_b   = (const float*)d_in[2];
    const float* rec_w   = (const float*)d_in[3];
    const float* fgt_w   = (const float*)d_in[4];
    const float* dec_w   = (const float*)d_in[5];
    const float* dec_b   = (const float*)d_in[6];
    const float* hinit_w = (const float*)d_in[7];
    const float* hinit_b = (const float*)d_in[8];
    float* out = (float*)d_out;

    reset_kernel<<<1, 32>>>();
    init_hidden_kernel<<<(B_ * NH + 255) / 256, 256>>>(hinit_w, hinit_b);

    dim3 eg(T_ * B_ / 32, NH / 64);
    enc_kernel<<<eg, 256>>>(x, enc_w, enc_b);

    cudaFuncSetAttribute(persist_kernel, cudaFuncAttributeMaxDynamicSharedMemorySize,
                         SMEM_BYTES);
    int writeHidden = (out_size >= T_ * B_ * NO + B_ * NH) ? 1 : 0;
    persist_kernel<<<NCTA, NTHR, SMEM_BYTES>>>(rec_w, fgt_w, dec_w, dec_b,
                                               hinit_w, hinit_b, out, writeHidden);
}

// round 16
// speedup vs baseline: 2.3764x; 1.4492x over previous
#include <cuda_runtime.h>
#include <cuda_bf16.h>
#include <math.h>

#define B_   128
#define T_   512
#define NI   64
#define NH   1024
#define NO   64

#define NCTA  132            // 2 b-halves x (64 rec + 2 dec); 1 CTA/SM
#define NTHR  256
#define BNH   (B_ * NH)
#define PSTR  36             // padded floats per P row
#define SM_B0 0
#define SMEM_BYTES 131072    // B build 128KB; P (74KB) reuses it during steps

// ---------------- scratch ------------------------------------------------------
__device__ float g_enc[(size_t)T_ * B_ * NH];      // [t][b][h] fp32
// hidden in MMA-fragment-major layout:
// [buf][split][((kk*8 + mtile)*32 + lane)*4 + reg] (uint = 2 bf16)
__device__ unsigned g_hA[3][2][65536];
__device__ unsigned g_done[2];
__device__ unsigned g_decc[2];

// ---------------- helpers ------------------------------------------------------
__device__ __forceinline__ unsigned smem_u32(const void* p) {
    unsigned a;
    asm("{ .reg .u64 t; cvta.to.shared.u64 t, %1; cvt.u32.u64 %0, t; }" : "=r"(a) : "l"(p));
    return a;
}
__device__ __forceinline__ void ldsm_x4t(unsigned r[4], unsigned addr) {
    asm volatile("ldmatrix.sync.aligned.m8n8.x4.trans.shared.b16 {%0,%1,%2,%3}, [%4];"
                 : "=r"(r[0]), "=r"(r[1]), "=r"(r[2]), "=r"(r[3]) : "r"(addr));
}
__device__ __forceinline__ void mma16816(float d[4], const unsigned a[4],
                                         unsigned b0, unsigned b1) {
    asm volatile(
        "mma.sync.aligned.m16n8k16.row.col.f32.bf16.bf16.f32 "
        "{%0,%1,%2,%3}, {%4,%5,%6,%7}, {%8,%9}, {%0,%1,%2,%3};"
        : "+f"(d[0]), "+f"(d[1]), "+f"(d[2]), "+f"(d[3])
        : "r"(a[0]), "r"(a[1]), "r"(a[2]), "r"(a[3]), "r"(b0), "r"(b1));
}
__device__ __forceinline__ void split_bf(float v, __nv_bfloat16& hi, __nv_bfloat16& lo) {
    hi = __float2bfloat16(v);
    lo = __float2bfloat16(v - __bfloat162float(hi));
}
__device__ __forceinline__ unsigned pack2(float a, float b) {
    __nv_bfloat162 t = __floats2bfloat162_rn(a, b);
    return *(unsigned*)&t;
}

// ---------------- reset + init --------------------------------------------------
__global__ void reset_kernel() {
    if (threadIdx.x < 2) { g_done[threadIdx.x] = 0; g_decc[threadIdx.x] = 0; }
}

__global__ void init_hidden_kernel(const float* __restrict__ hinit_w,
                                   const float* __restrict__ hinit_b) {
    int idx = blockIdx.x * blockDim.x + threadIdx.x;
    if (idx < B_ * NH) {
        int b = idx >> 10, h = idx & 1023;
        float v = hinit_w[h] + hinit_b[h];
        __nv_bfloat16 hi, lo;
        split_bf(v, hi, lo);
        int kk = h >> 4, mtile = b >> 4;
        int lanei = (b & 7) * 4 + ((h >> 1) & 3);
        int regi = ((b >> 3) & 1) + 2 * ((h >> 3) & 1);
        size_t e = ((size_t)((kk * 8 + mtile) * 32 + lanei) * 4 + regi) * 2 + (h & 1);
        ((__nv_bfloat16*)g_hA[0][0])[e] = hi;
        ((__nv_bfloat16*)g_hA[0][1])[e] = lo;
    }
}

// ---------------- encoder GEMM (one-shot), fp32 [t][b][h] ------------------------
__global__ void __launch_bounds__(256) enc_kernel(const float* __restrict__ x,
                                                  const float* __restrict__ enc_w,
                                                  const float* __restrict__ enc_b) {
    __shared__ float xs[32][NI + 1];
    __shared__ float ws[64][NI + 1];
    const int tid = threadIdx.x;
    const int tb0 = blockIdx.x * 32;
    const int h0  = blockIdx.y * 64;

    for (int i = tid; i < 32 * NI; i += 256) {
        int r = i >> 6, c = i & 63;
        int tb = tb0 + r;
        int t = tb >> 7, b = tb & 127;
        xs[r][c] = x[(size_t)b * (T_ * NI) + t * NI + c];
    }
    for (int i = tid; i < 64 * NI; i += 256) {
        int r = i >> 6, c = i & 63;
        ws[r][c] = enc_w[(h0 + r) * NI + c];
    }
    __syncthreads();

    const int rg = tid & 7;
    const int hg = tid >> 3;
    float acc[4][2] = {};
#pragma unroll
    for (int k = 0; k < NI; k++) {
        float w0 = ws[hg * 2 + 0][k];
        float w1 = ws[hg * 2 + 1][k];
#pragma unroll
        for (int j = 0; j < 4; j++) {
            float xv = xs[rg * 4 + j][k];
            acc[j][0] += xv * w0;
            acc[j][1] += xv * w1;
        }
    }
#pragma unroll
    for (int j = 0; j < 4; j++) {
        int tb = tb0 + rg * 4 + j;
#pragma unroll
        for (int q = 0; q < 2; q++) {
            int h = h0 + hg * 2 + q;
            g_enc[(size_t)tb * NH + h] = acc[j][q] + enc_b[h];
        }
    }
}

// ---------------- persistent mma.sync recurrent kernel ---------------------------
// CTA: jc = bid>>1 (0..65), bh = bid&1.
//   jc<64: rec tile, h cols jc*16..+15 (B cols interleaved R,F); jc>=64: dec tile.
// Warps: ko = wid (k-octant of 128). Per warp: n32, 4 m16 tiles, 8 k16 tiles.
// B fragments (hi+lo, 128 regs) resident across all steps.
// A fragments loaded DIRECTLY from fragment-major gmem (1 LDG.128 each).
__global__ void __launch_bounds__(NTHR) persist_kernel(const float* __restrict__ rec_w,
                                                       const float* __restrict__ fgt_w,
                                                       const float* __restrict__ dec_w,
                                                       const float* __restrict__ dec_b,
                                                       const float* __restrict__ hinit_w,
                                                       const float* __restrict__ hinit_b,
                                                       float* __restrict__ out,
                                                       int writeHidden) {
    extern __shared__ __align__(128) char smem[];
    const unsigned sbase = smem_u32(smem);
    float* Pf = (float*)smem;
    const int tid  = threadIdx.x;
    const int lane = tid & 31;
    const int ko   = tid >> 5;           // warp = k-octant
    const int bid  = blockIdx.x;
    const int jc   = bid >> 1;
    const int bh   = bid & 1;
    const bool isDec = (jc >= 64);
    const int h0   = jc * 16;
    const int oc0  = (jc - 64) * 32;

    const int matid = lane >> 3;
    const int r8    = lane & 7;

    // ---- build B mats in smem (temporary), then preload fragments ----
    for (int i = tid; i < 32 * NH; i += NTHR) {
        int col = i >> 10, k = i & 1023;
        float w;
        if (!isDec) w = (col & 1) ? fgt_w[(h0 + (col >> 1)) * NH + k]
                                  : rec_w[(h0 + (col >> 1)) * NH + k];
        else        w = dec_w[(oc0 + col) * NH + k];
        __nv_bfloat16 hi, lo;
        split_bf(w, hi, lo);
        unsigned unit = (unsigned)((k >> 4) * 8 + (col >> 3) * 2 + ((k >> 3) & 1));
        unsigned off  = unit * 128 + (k & 7) * 16 + (col & 7) * 2;
        *(__nv_bfloat16*)(smem + SM_B0 + off) = hi;
        *(__nv_bfloat16*)(smem + SM_B0 + 65536 + off) = lo;
    }
    __syncthreads();

    unsigned bHf[8][8], bLf[8][8];
#pragma unroll
    for (int kk = 0; kk < 8; kk++) {
#pragma unroll
        for (int ct = 0; ct < 2; ct++) {
            unsigned boff = (unsigned)(((ko * 8 + kk) * 8 + ct * 4 + matid) * 128 + r8 * 16);
            ldsm_x4t(&bHf[kk][ct * 4], sbase + SM_B0 + boff);
            ldsm_x4t(&bLf[kk][ct * 4], sbase + SM_B0 + 65536 + boff);
        }
    }
    __syncthreads();   // B smem dead; region reused as P

    // ---- epilogue ownership: thread -> (b, 4 h/col-pairs) ----
    const int eb  = tid >> 2;                 // local b 0..63
    const int ehl = (tid & 3) * 4;            // first of 4 owned h (local)
    const int gb  = bh * 64 + eb;             // global b
    float hold[4];
    if (!isDec) {
#pragma unroll
        for (int i = 0; i < 4; i++)
            hold[i] = __ldg(hinit_w + h0 + ehl + i) + __ldg(hinit_b + h0 + ehl + i);
    }
    float db[8];
    if (isDec) {
#pragma unroll
        for (int i = 0; i < 8; i++)
            db[i] = __ldg(dec_b + oc0 + ehl * 2 + i);
    }
    // fragment-major write coords (rec)
    const unsigned baseW = (unsigned)(jc * 8 + (gb >> 4)) * 32;
    const int lane0 = (gb & 7) * 4 + ((ehl >> 1) & 3);
    const int regi  = ((gb >> 3) & 1) + 2 * ((ehl >> 3) & 1);
    const unsigned widx = (baseW + lane0) * 4 + regi;

    for (int t = 0; t <= T_; t++) {
        const bool work = isDec || (t < T_);
        if (work) {
            const int cur = t % 3, nxtb = (t + 1) % 3;

            // ---- wait: all 64 rec producers of this b-half finished step t-1 ----
            if (tid == 0 && t > 0) {
                unsigned target = 64u * (unsigned)t;
                while (*(volatile unsigned*)&g_done[bh] < target) __nanosleep(20);
                __threadfence();
            }
            __syncthreads();

            // epilogue operand prefetch
            float4 e4;
            if (!isDec)
                e4 = __ldcg((const float4*)(g_enc + (size_t)t * BNH + (size_t)gb * NH + h0 + ehl));

            float acc[4][4][4];
#pragma unroll
            for (int m = 0; m < 4; m++)
#pragma unroll
                for (int g = 0; g < 4; g++)
#pragma unroll
                    for (int q = 0; q < 4; q++) acc[m][g][q] = 0.f;

            const unsigned* Ah = g_hA[cur][0];
            const unsigned* Al = g_hA[cur][1];

            // ================= K loop: direct-LDG A fragments =================
#pragma unroll
            for (int kk = 0; kk < 8; kk++) {
                const int kg = ko * 8 + kk;
#pragma unroll
                for (int mt = 0; mt < 4; mt++) {
                    const int mtile = bh * 4 + mt;
                    const unsigned fidx = ((unsigned)(kg * 8 + mtile) * 32 + lane) * 4;
                    uint4 AH = __ldcg((const uint4*)(Ah + fidx));
                    uint4 AL = __ldcg((const uint4*)(Al + fidx));
                    unsigned ah[4] = {AH.x, AH.y, AH.z, AH.w};
                    unsigned al[4] = {AL.x, AL.y, AL.z, AL.w};
                    mma16816(acc[mt][0], ah, bHf[kk][0], bHf[kk][1]);
                    mma16816(acc[mt][1], ah, bHf[kk][2], bHf[kk][3]);
                    mma16816(acc[mt][2], ah, bHf[kk][4], bHf[kk][5]);
                    mma16816(acc[mt][3], ah, bHf[kk][6], bHf[kk][7]);
                    mma16816(acc[mt][0], al, bHf[kk][0], bHf[kk][1]);
                    mma16816(acc[mt][1], al, bHf[kk][2], bHf[kk][3]);
                    mma16816(acc[mt][2], al, bHf[kk][4], bHf[kk][5]);
                    mma16816(acc[mt][3], al, bHf[kk][6], bHf[kk][7]);
                    mma16816(acc[mt][0], ah, bLf[kk][0], bLf[kk][1]);
                    mma16816(acc[mt][1], ah, bLf[kk][2], bLf[kk][3]);
                    mma16816(acc[mt][2], ah, bLf[kk][4], bLf[kk][5]);
                    mma16816(acc[mt][3], ah, bLf[kk][6], bLf[kk][7]);
                }
            }

            // ---- store partials into P[ko][b][col] ----
#pragma unroll
            for (int mt = 0; mt < 4; mt++) {
#pragma unroll
                for (int g = 0; g < 4; g++) {
                    int c = g * 8 + 2 * (lane & 3);
                    int rA = mt * 16 + (lane >> 2);
                    float* p = Pf + ko * (64 * PSTR) + rA * PSTR + c;
                    *(float2*)p = make_float2(acc[mt][g][0], acc[mt][g][1]);
                    *(float2*)(p + 8 * PSTR) = make_float2(acc[mt][g][2], acc[mt][g][3]);
                }
            }
            __syncthreads();

            // ---- dec guard / signal ----
            if (tid == 0) {
                if (isDec) {
                    atomicAdd(&g_decc[bh], 1u);
                } else if (t >= 2) {
                    unsigned dt = 2u * (unsigned)(t - 1);
                    while (*(volatile unsigned*)&g_decc[bh] < dt) __nanosleep(20);
                    __threadfence();
                }
            }

            // ---- reduce 8 k-octants ----
            float R[4], F[4];
            {
                const float* pb = Pf + eb * PSTR + 2 * ehl;
                float4 q0 = *(const float4*)pb;
                float4 q1 = *(const float4*)(pb + 4);
                R[0] = q0.x; F[0] = q0.y; R[1] = q0.z; F[1] = q0.w;
                R[2] = q1.x; F[2] = q1.y; R[3] = q1.z; F[3] = q1.w;
#pragma unroll
                for (int k2 = 1; k2 < 8; k2++) {
                    const float* pk = pb + k2 * (64 * PSTR);
                    float4 s0 = *(const float4*)pk;
                    float4 s1 = *(const float4*)(pk + 4);
                    R[0] += s0.x; F[0] += s0.y; R[1] += s0.z; F[1] += s0.w;
                    R[2] += s1.x; F[2] += s1.y; R[3] += s1.z; F[3] += s1.w;
                }
            }

            // ---- fused epilogue ----
            if (!isDec) {
                const float ev[4] = {e4.x, e4.y, e4.z, e4.w};
                float hv[4], lov[4];
#pragma unroll
                for (int i = 0; i < 4; i++) {
                    float f = 1.0f / (1.0f + __expf(-F[i]));
                    float sgn = ev[i] + R[i];
                    float hn = sgn / (1.0f + fabsf(sgn));
                    float v = (1.0f - f) * hold[i] + f * hn;
                    hold[i] = v;
                    hv[i] = v;
                    __nv_bfloat16 hb16 = __float2bfloat16(v);
                    lov[i] = v - __bfloat162float(hb16);
                }
                unsigned* wH = g_hA[nxtb][0];
                unsigned* wL = g_hA[nxtb][1];
                wH[widx]     = pack2(hv[0], hv[1]);
                wH[widx + 4] = pack2(hv[2], hv[3]);
                wL[widx]     = pack2(lov[0], lov[1]);
                wL[widx + 4] = pack2(lov[2], lov[3]);
                __threadfence();
                __syncthreads();
                if (tid == 0) atomicAdd(&g_done[bh], 1u);
            } else if (t >= 1) {
                float* op = out + (size_t)(t - 1) * (B_ * NO) + (size_t)gb * NO + oc0 + ehl * 2;
                float4 v0 = make_float4(R[0] + db[0], F[0] + db[1], R[1] + db[2], F[1] + db[3]);
                float4 v1 = make_float4(R[2] + db[4], F[2] + db[5], R[3] + db[6], F[3] + db[7]);
                *(float4*)op = v0;
                *(float4*)(op + 4) = v1;
                __syncthreads();   // done reading P before next step's STS
            } else {
                __syncthreads();
            }
        }
        if (t == T_) break;
    }

    // ---- final hidden -> out tail [b][h] (from registers) ----
    if (writeHidden && !isDec) {
        float* dst = out + (size_t)T_ * B_ * NO + (size_t)gb * NH + h0 + ehl;
        *(float4*)dst = make_float4(hold[0], hold[1], hold[2], hold[3]);
    }
}

// --------------------------------------------------------------------------------
extern "C" void kernel_launch(void* const* d_in, const int* in_sizes, int n_in,
                              void* d_out, int out_size) {
    const float* x       = (const float*)d_in[0];
    const float* enc_w   = (const float*)d_in[1];
    const float* enc_b   = (const float*)d_in[2];
    const float* rec_w   = (const float*)d_in[3];
    const float* fgt_w   = (const float*)d_in[4];
    const float* dec_w   = (const float*)d_in[5];
    const float* dec_b   = (const float*)d_in[6];
    const float* hinit_w = (const float*)d_in[7];
    const float* hinit_b = (const float*)d_in[8];
    float* out = (float*)d_out;

    reset_kernel<<<1, 32>>>();
    init_hidden_kernel<<<(B_ * NH + 255) / 256, 256>>>(hinit_w, hinit_b);

    dim3 eg(T_ * B_ / 32, NH / 64);
    enc_kernel<<<eg, 256>>>(x, enc_w, enc_b);

    cudaFuncSetAttribute(persist_kernel, cudaFuncAttributeMaxDynamicSharedMemorySize,
                         SMEM_BYTES);
    int writeHidden = (out_size >= T_ * B_ * NO + B_ * NH) ? 1 : 0;
    persist_kernel<<<NCTA, NTHR, SMEM_BYTES>>>(rec_w, fgt_w, dec_w, dec_b,
                                               hinit_w, hinit_b, out, writeHidden);
}